// round 5
// baseline (speedup 1.0000x reference)
#include <cuda_runtime.h>
#include <cuda_bf16.h>
#include <cstdint>

// ---------------------------------------------------------------------------
// Arch-path detection: tcgen05 is only legal in arch-specific / family device
// passes (sm_103a / sm_103f). The harness's compute_103 PTX pass must never
// see tcgen05. Exactly one of the two GEMM kernels has a body per pass.
// ---------------------------------------------------------------------------
#if defined(__CUDA_ARCH_SPECIFIC__) || defined(__CUDA_ARCH_FAMILY_SPECIFIC__)
#define TCG_OK 1
#else
#define TCG_OK 0
#endif

// ---------------------------------------------------------------------------
// Problem dims
// ---------------------------------------------------------------------------
#define T_DIM 8192
#define I_DIM 4096
#define O_DIM 4096

// Static scratch (allocation-free rule): double-bf16 split of x and dequant W
__device__ __nv_bfloat16 g_Ah[(size_t)T_DIM * I_DIM];
__device__ __nv_bfloat16 g_Al[(size_t)T_DIM * I_DIM];
__device__ __nv_bfloat16 g_Bh[(size_t)O_DIM * I_DIM];
__device__ __nv_bfloat16 g_Bl[(size_t)O_DIM * I_DIM];

// ---------------------------------------------------------------------------
// Portable PTX helpers
// ---------------------------------------------------------------------------
__device__ __forceinline__ uint32_t smem_to_u32(const void* p) {
    uint32_t a;
    asm("{ .reg .u64 t; cvta.to.shared.u64 t, %1; cvt.u32.u64 %0, t; }" : "=r"(a) : "l"(p));
    return a;
}

__device__ __forceinline__ void cp_async16(uint32_t s, const void* g) {
    asm volatile("cp.async.cg.shared.global [%0], [%1], 16;" :: "r"(s), "l"(g) : "memory");
}
#define CP_COMMIT() asm volatile("cp.async.commit_group;" ::: "memory")
#define CP_WAIT_GROUP_3() asm volatile("cp.async.wait_group 3;" ::: "memory")

#define SMEM_SWIZZLE_128B(byte_offset) ((byte_offset) ^ (((byte_offset) >> 3) & 0x70))

// ldmatrix / mma.sync — baseline PTX, legal on .target sm_103
__device__ __forceinline__ void ldsm_x4(uint32_t* r, uint32_t addr) {
    asm volatile("ldmatrix.sync.aligned.m8n8.x4.shared.b16 {%0,%1,%2,%3}, [%4];"
                 : "=r"(r[0]), "=r"(r[1]), "=r"(r[2]), "=r"(r[3]) : "r"(addr));
}
__device__ __forceinline__ void mma16816(float* d, const uint32_t* a, const uint32_t* b) {
    asm volatile(
        "mma.sync.aligned.m16n8k16.row.col.f32.bf16.bf16.f32 "
        "{%0,%1,%2,%3}, {%4,%5,%6,%7}, {%8,%9}, {%0,%1,%2,%3};"
        : "+f"(d[0]), "+f"(d[1]), "+f"(d[2]), "+f"(d[3])
        : "r"(a[0]), "r"(a[1]), "r"(a[2]), "r"(a[3]), "r"(b[0]), "r"(b[1]));
}

// ---------------------------------------------------------------------------
// Exact NVFP4 quantization math (bit-identical to the jax fp32 reference;
// power-of-two steps built exactly so --use_fast_math cannot perturb them).
// ilogbf-vs-fp32-log2 boundary cases round to the same quantized value.
// ---------------------------------------------------------------------------
__device__ __forceinline__ float q_e4m3(float x) {
    float s = (x > 0.f) ? 1.f : ((x < 0.f) ? -1.f : 0.f);
    float ax = fminf(fabsf(x), 448.0f);
    int e = -6;
    if (ax > 0.f) {
        e = ilogbf(ax);
        if (e < -6) e = -6;
        if (e > 8)  e = 8;
    }
    float step  = __int_as_float((e + 127) << 23);   // 2^e  (exact)
    float rstep = __int_as_float((127 - e) << 23);   // 2^-e (exact)
    float q = rintf(ax * rstep * 8.0f) * 0.125f * step;
    return s * q;
}

__device__ __forceinline__ float q_e2m1(float x) {
    float s = (x > 0.f) ? 1.f : ((x < 0.f) ? -1.f : 0.f);
    float ax = fminf(fabsf(x), 6.0f);
    int e = 0;
    if (ax > 0.f) {
        e = ilogbf(ax);
        if (e < 0) e = 0;
        if (e > 2) e = 2;
    }
    float step  = __int_as_float((e + 127) << 23);
    float rstep = __int_as_float((127 - e) << 23);
    float q = rintf(ax * rstep * 2.0f) * 0.5f * step;
    return s * q;
}

// ---------------------------------------------------------------------------
// Prep kernel 1: dequantize W and split into (Bh, Bl) double-bf16
// ---------------------------------------------------------------------------
__global__ void dequant_weight_kernel(const float* __restrict__ w,
                                      const float* __restrict__ pba,
                                      const float* __restrict__ gam) {
    size_t idx = (size_t)blockIdx.x * blockDim.x + threadIdx.x;
    if (idx >= (size_t)O_DIM * I_DIM) return;
    size_t o = idx >> 12;
    int i = (int)(idx & (I_DIM - 1));

    float gscale = __fdiv_rn(gam[0], 2688.0f);                   // /(6*448)
    float bf     = __fdiv_rn(pba[o * (I_DIM / 16) + (i >> 4)], 6.0f);
    float bs     = q_e4m3(__fdiv_rn(bf, gscale)) * gscale;

    float wdq = 0.0f;
    if (bs > 0.0f) {
        float wq = __fdiv_rn(w[idx], fmaxf(bs, 1e-30f));
        wdq = q_e2m1(wq) * bs;
    }
    __nv_bfloat16 h = __float2bfloat16_rn(wdq);
    float lo = wdq - __bfloat162float(h);   // exact in fp32
    g_Bh[idx] = h;
    g_Bl[idx] = __float2bfloat16_rn(lo);
}

// ---------------------------------------------------------------------------
// Prep kernel 2: split x into (Ah, Al) double-bf16
// ---------------------------------------------------------------------------
__global__ void split_x_kernel(const float* __restrict__ x) {
    size_t idx = (size_t)blockIdx.x * blockDim.x + threadIdx.x;
    if (idx >= (size_t)T_DIM * I_DIM) return;
    float v = x[idx];
    __nv_bfloat16 h = __float2bfloat16_rn(v);
    float lo = v - __bfloat162float(h);
    g_Ah[idx] = h;
    g_Al[idx] = __float2bfloat16_rn(lo);
}

// ===========================================================================
// PATH A: tcgen05 GEMM (only compiled in arch-specific/family device passes)
// ===========================================================================
constexpr int BM = 128;
constexpr int BN = 256;
constexpr int BK = 64;
constexpr int NCH = 3 * (I_DIM / BK);          // 192 chunks (3-term split)
constexpr int NSTG = 4;
constexpr int A_BYTES = BM * 128;              // 16 KB
constexpr int B_BYTES = BN * 128;              // 32 KB
constexpr int STG_BYTES = A_BYTES + B_BYTES;   // 48 KB
constexpr int SM_TMEMPTR = 0;
constexpr int SM_MBAR = 16;
constexpr int SM_TILES = 1024;
constexpr int SMEM_DYN = SM_TILES + NSTG * STG_BYTES;   // 197632 B

constexpr uint32_t IDESC =
    (1u << 4) | (1u << 7) | (1u << 10) | ((BN / 8) << 17) | ((BM / 16) << 24);

static constexpr uint64_t SMEM_DESC_BASE_SW128 =
    (uint64_t(2) << 61) | (uint64_t(1) << 46) | (uint64_t(64) << 32) | (uint64_t(1) << 16);
#define MAKE_SMEM_DESC(base_addr) \
    (SMEM_DESC_BASE_SW128 | ((uint64_t)((base_addr) >> 4) & 0x3FFF))

#if TCG_OK
__device__ __forceinline__ uint32_t elect_one_pred() {
    uint32_t pred;
    asm volatile(
        "{\n\t.reg .pred p;\n\telect.sync _|p, 0xFFFFFFFF;\n\tselp.b32 %0, 1, 0, p;\n\t}"
        : "=r"(pred));
    return pred;
}

#define MBARRIER_INIT(addr, count) \
    asm volatile("mbarrier.init.shared.b64 [%0], %1;" :: "r"((uint32_t)(addr)), "r"((uint32_t)(count)) : "memory")

#define MBARRIER_WAIT_PARITY(mbar_smem_addr, phase_parity) do { \
    uint32_t _mbar = (uint32_t)(mbar_smem_addr); \
    uint32_t _parity = (uint32_t)(phase_parity); \
    uint32_t _done; \
    asm volatile( \
        "{\n\t.reg .pred p;\n\t" \
        "mbarrier.try_wait.parity.acquire.cta.shared::cta.b64 p, [%1], %2;\n\t" \
        "selp.b32 %0, 1, 0, p;\n\t}" \
        : "=r"(_done) : "r"(_mbar), "r"(_parity) : "memory"); \
    if (!_done) { \
        asm volatile( \
            "{\n\t.reg .pred P1;\n\t" \
            "WAIT_LOOP_%=:\n\t" \
            "mbarrier.try_wait.parity.acquire.cta.shared::cta.b64 P1, [%0], %1, 0x989680;\n\t" \
            "@P1 bra.uni WAIT_DONE_%=;\n\t" \
            "bra.uni WAIT_LOOP_%=;\n\t" \
            "WAIT_DONE_%=:\n\t}" \
            :: "r"(_mbar), "r"(_parity) : "memory"); \
    } \
} while(0)

#define TCGEN05_ALLOC(smem_result_addr, nCols) \
    asm volatile("tcgen05.alloc.cta_group::1.sync.aligned.shared::cta.b32 [%0], %1;" \
        :: "r"((uint32_t)(smem_result_addr)), "r"((uint32_t)(nCols)) : "memory")
#define TCGEN05_DEALLOC(tmem_addr, nCols) \
    asm volatile("tcgen05.dealloc.cta_group::1.sync.aligned.b32 %0, %1;" \
        :: "r"(tmem_addr), "r"((uint32_t)(nCols)))
#define TCGEN05_RELINQUISH_ALLOC_PERMIT() \
    asm volatile("tcgen05.relinquish_alloc_permit.cta_group::1.sync.aligned;")
#define TCGEN05_COMMIT(mbar_smem_addr) \
    asm volatile("tcgen05.commit.cta_group::1.mbarrier::arrive::one.shared::cluster.b64 [%0];" \
        :: "r"((uint32_t)(mbar_smem_addr)) : "memory")
#define TCGEN05_WAIT_LD() asm volatile("tcgen05.wait::ld.sync.aligned;" ::: "memory")
#define TCGEN05_FENCE_AFTER() asm volatile("tcgen05.fence::after_thread_sync;" ::: "memory")
#define FENCE_PROXY_ASYNC_SHARED_CTA() asm volatile("fence.proxy.async.shared::cta;" ::: "memory")

#define TCGEN05_LD_32X32B_X32(r, tmem_addr) \
    asm volatile( \
        "tcgen05.ld.sync.aligned.32x32b.x32.b32 " \
        "{%0, %1, %2, %3, %4, %5, %6, %7, " \
        " %8, %9, %10, %11, %12, %13, %14, %15, " \
        " %16, %17, %18, %19, %20, %21, %22, %23, " \
        " %24, %25, %26, %27, %28, %29, %30, %31}, [%32];" \
        : "=r"((r)[0]),  "=r"((r)[1]),  "=r"((r)[2]),  "=r"((r)[3]), \
          "=r"((r)[4]),  "=r"((r)[5]),  "=r"((r)[6]),  "=r"((r)[7]), \
          "=r"((r)[8]),  "=r"((r)[9]),  "=r"((r)[10]), "=r"((r)[11]), \
          "=r"((r)[12]), "=r"((r)[13]), "=r"((r)[14]), "=r"((r)[15]), \
          "=r"((r)[16]), "=r"((r)[17]), "=r"((r)[18]), "=r"((r)[19]), \
          "=r"((r)[20]), "=r"((r)[21]), "=r"((r)[22]), "=r"((r)[23]), \
          "=r"((r)[24]), "=r"((r)[25]), "=r"((r)[26]), "=r"((r)[27]), \
          "=r"((r)[28]), "=r"((r)[29]), "=r"((r)[30]), "=r"((r)[31]) \
        : "r"(tmem_addr))

__device__ __forceinline__ void mma_f16_ss(uint32_t d, uint64_t ad, uint64_t bd,
                                           uint32_t idesc, bool acc) {
    uint32_t en = acc ? 1u : 0u;
    asm volatile(
        "{\n\t.reg .pred p;\n\tsetp.ne.u32 p, %5, 0;\n\t"
        "tcgen05.mma.cta_group::1.kind::f16 [%0], %1, %2, %3, {%4, %4, %4, %4}, p;\n\t}"
        :: "r"(d), "l"(ad), "l"(bd), "r"(idesc), "r"(0u), "r"(en)
        : "memory");
}
#endif  // TCG_OK

__global__ void __launch_bounds__(256, 1)
nvfp4_gemm_tcgen05(float* __restrict__ out) {
#if TCG_OK
    extern __shared__ char smem[];
    const uint32_t sb = smem_to_u32(smem);
    const int tid = threadIdx.x;
    const int wid = tid >> 5;
    const int lid = tid & 31;

    if (wid == 0) TCGEN05_ALLOC(sb + SM_TMEMPTR, 256);
    if (tid == 0) {
#pragma unroll
        for (int s = 0; s < NSTG; s++) MBARRIER_INIT(sb + SM_MBAR + 8 * s, 1);
    }
    __syncthreads();
    uint32_t tmem;
    asm volatile("ld.shared.b32 %0, [%1];" : "=r"(tmem) : "r"(sb + SM_TMEMPTR));

    const size_t m0 = (size_t)blockIdx.y * BM;
    const size_t n0 = (size_t)blockIdx.x * BN;

    uint32_t a_soff[4], b_soff[8];
    size_t a_goff[4], b_goff[8];
#pragma unroll
    for (int i = 0; i < 4; i++) {
        int idx = tid + i * 256;
        int r = idx >> 3, c16 = idx & 7;
        a_soff[i] = SMEM_SWIZZLE_128B((uint32_t)(r * 128 + c16 * 16));
        a_goff[i] = (m0 + r) * (size_t)I_DIM + (size_t)c16 * 8;
    }
#pragma unroll
    for (int i = 0; i < 8; i++) {
        int idx = tid + i * 256;
        int r = idx >> 3, c16 = idx & 7;
        b_soff[i] = SMEM_SWIZZLE_128B((uint32_t)(r * 128 + c16 * 16));
        b_goff[i] = (n0 + r) * (size_t)I_DIM + (size_t)c16 * 8;
    }

    auto load_chunk = [&](int c) {
        int s = c & (NSTG - 1);
        uint32_t sa  = sb + SM_TILES + s * STG_BYTES;
        uint32_t sbB = sa + A_BYTES;
        int pass = c >> 6;
        size_t kk = (size_t)(c & 63) * BK;
        const __nv_bfloat16* Ab = (pass == 1) ? g_Al : g_Ah;
        const __nv_bfloat16* Bb = (pass == 2) ? g_Bl : g_Bh;
#pragma unroll
        for (int i = 0; i < 4; i++) cp_async16(sa + a_soff[i], Ab + a_goff[i] + kk);
#pragma unroll
        for (int i = 0; i < 8; i++) cp_async16(sbB + b_soff[i], Bb + b_goff[i] + kk);
    };

#pragma unroll 1
    for (int c = 0; c < NSTG - 1; c++) { load_chunk(c); CP_COMMIT(); }

#pragma unroll 1
    for (int k = 0; k < NCH; k++) {
        int cl = k + NSTG - 1;
        if (cl < NCH) {
            if (cl >= NSTG) {
                int s = cl & (NSTG - 1);
                int par = ((cl >> 2) - 1) & 1;
                MBARRIER_WAIT_PARITY(sb + SM_MBAR + 8 * s, par);
            }
            load_chunk(cl);
        }
        CP_COMMIT();
        CP_WAIT_GROUP_3();
        __syncthreads();
        if (wid == 0) {
            FENCE_PROXY_ASYNC_SHARED_CTA();
            if (elect_one_pred()) {
                int s = k & (NSTG - 1);
                uint32_t sa = sb + SM_TILES + s * STG_BYTES;
                uint64_t ad = MAKE_SMEM_DESC(sa);
                uint64_t bd = MAKE_SMEM_DESC(sa + A_BYTES);
#pragma unroll
                for (int j = 0; j < 4; j++)
                    mma_f16_ss(tmem, ad + j * 2, bd + j * 2, IDESC, !(k == 0 && j == 0));
                TCGEN05_COMMIT(sb + SM_MBAR + 8 * s);
            }
        }
    }

    {
        int s = (NCH - 1) & (NSTG - 1);
        int par = ((NCH - 1) >> 2) & 1;
        MBARRIER_WAIT_PARITY(sb + SM_MBAR + 8 * s, par);
    }
    TCGEN05_FENCE_AFTER();

    if (wid < 4) {
        size_t row = m0 + (size_t)(wid * 32 + lid);
        float* op = out + row * (size_t)O_DIM + n0;
#pragma unroll 1
        for (int cb = 0; cb < 8; cb++) {
            uint32_t r[32];
            TCGEN05_LD_32X32B_X32(r, tmem + cb * 32);
            TCGEN05_WAIT_LD();
#pragma unroll
            for (int q = 0; q < 8; q++) {
                float4 v;
                v.x = __uint_as_float(r[q * 4 + 0]);
                v.y = __uint_as_float(r[q * 4 + 1]);
                v.z = __uint_as_float(r[q * 4 + 2]);
                v.w = __uint_as_float(r[q * 4 + 3]);
                *reinterpret_cast<float4*>(op + cb * 32 + q * 4) = v;
            }
        }
    }

    __syncthreads();
    if (wid == 0) {
        TCGEN05_RELINQUISH_ALLOC_PERMIT();
        TCGEN05_DEALLOC(tmem, 256);
    }
#endif  // TCG_OK
}

// ===========================================================================
// PATH B: portable mma.sync (HMMA) GEMM — compiled when tcgen05 is NOT legal
// ===========================================================================
constexpr int FBM = 128, FBN = 128, FBK = 64;
constexpr int FNCH = 3 * (I_DIM / FBK);        // 192 chunks
constexpr int FSTG = 4;
constexpr int F_ABYTES = FBM * 128;            // 16 KB
constexpr int F_STGB = F_ABYTES + FBN * 128;   // 32 KB
constexpr int F_SMEM = FSTG * F_STGB;          // 131072 B

__global__ void __launch_bounds__(256, 1)
nvfp4_gemm_mmasync(float* __restrict__ out) {
#if !TCG_OK
    extern __shared__ char smem[];
    const uint32_t sb = smem_to_u32(smem);
    const int tid = (int)threadIdx.x;
    const int wid = tid >> 5;
    const int lane = tid & 31;
    const int wm = wid & 1;          // 2 warps over M (64 rows each)
    const int wn = wid >> 1;         // 4 warps over N (32 cols each)

    const size_t m0 = (size_t)blockIdx.y * FBM;
    const size_t n0 = (size_t)blockIdx.x * FBN;

    // --- loader slots: 8 x 16B per thread (A rows then B rows, SW128) ---
    uint32_t soff[8];
    size_t goff[8];
#pragma unroll
    for (int i = 0; i < 8; i++) {
        int idx = tid + i * 256;
        if (i < 4) {
            int r = idx >> 3, c16 = idx & 7;
            soff[i] = SMEM_SWIZZLE_128B((uint32_t)(r * 128 + c16 * 16));
            goff[i] = (m0 + r) * (size_t)I_DIM + (size_t)c16 * 8;
        } else {
            int idx2 = idx - 1024;
            int r = idx2 >> 3, c16 = idx2 & 7;
            soff[i] = (uint32_t)F_ABYTES + SMEM_SWIZZLE_128B((uint32_t)(r * 128 + c16 * 16));
            goff[i] = (n0 + r) * (size_t)I_DIM + (size_t)c16 * 8;
        }
    }

    auto load_chunk = [&](int c) {
        int s = c & (FSTG - 1);
        uint32_t base = sb + s * F_STGB;
        int pass = c >> 6;                        // 0:(Ah,Bh) 1:(Al,Bh) 2:(Ah,Bl)
        size_t kk = (size_t)(c & 63) * FBK;
        const __nv_bfloat16* Ab = (pass == 1) ? g_Al : g_Ah;
        const __nv_bfloat16* Bb = (pass == 2) ? g_Bl : g_Bh;
#pragma unroll
        for (int i = 0; i < 4; i++) cp_async16(base + soff[i], Ab + goff[i] + kk);
#pragma unroll
        for (int i = 4; i < 8; i++) cp_async16(base + soff[i], Bb + goff[i] + kk);
    };

    // --- ldmatrix lane addressing (precomputed row terms) ---
    // A frag (m16k16): tiles = (rows0-7,k0-7),(rows8-15,k0-7),(rows0-7,k8-15),(rows8-15,k8-15)
    uint32_t arow128[4], axor[4];
    const uint32_t ahix = (uint32_t)((lane >> 4) * 16);
#pragma unroll
    for (int i = 0; i < 4; i++) {
        int row = wm * 64 + i * 16 + (lane & 7) + ((lane >> 3) & 1) * 8;
        arow128[i] = (uint32_t)(row * 128);
        axor[i] = (uint32_t)((row & 7) << 4);
    }
    // B frag pair (n16k16): tiles = (n0-7,k0-7),(n0-7,k8-15),(n8-15,k0-7),(n8-15,k8-15)
    uint32_t brow128[2], bxor[2];
    const uint32_t bhix = (uint32_t)(((lane >> 3) & 1) * 16);
#pragma unroll
    for (int jj = 0; jj < 2; jj++) {
        int row = wn * 32 + jj * 16 + (lane & 7) + ((lane >> 4) & 1) * 8;
        brow128[jj] = (uint32_t)(row * 128);
        bxor[jj] = (uint32_t)((row & 7) << 4);
    }

    float c[4][4][4];
#pragma unroll
    for (int i = 0; i < 4; i++)
#pragma unroll
        for (int j = 0; j < 4; j++)
#pragma unroll
            for (int r = 0; r < 4; r++) c[i][j][r] = 0.0f;

    // --- prologue: fill 4 stages ---
#pragma unroll 1
    for (int cch = 0; cch < FSTG; cch++) { load_chunk(cch); CP_COMMIT(); }

    // --- mainloop ---
#pragma unroll 1
    for (int k = 0; k < FNCH; k++) {
        CP_WAIT_GROUP_3();
        __syncthreads();

        uint32_t Abase = sb + (uint32_t)((k & (FSTG - 1)) * F_STGB);
        uint32_t Bbase = Abase + F_ABYTES;
#pragma unroll
        for (int q = 0; q < 4; q++) {
            uint32_t qa = (uint32_t)(q * 32) + ahix;
            uint32_t qb = (uint32_t)(q * 32) + bhix;
            uint32_t a[4][4], b[2][4];
#pragma unroll
            for (int i = 0; i < 4; i++)
                ldsm_x4(a[i], Abase + arow128[i] + (qa ^ axor[i]));
#pragma unroll
            for (int jj = 0; jj < 2; jj++)
                ldsm_x4(b[jj], Bbase + brow128[jj] + (qb ^ bxor[jj]));
#pragma unroll
            for (int i = 0; i < 4; i++) {
#pragma unroll
                for (int jj = 0; jj < 2; jj++) {
                    mma16816(c[i][2 * jj + 0], a[i], &b[jj][0]);
                    mma16816(c[i][2 * jj + 1], a[i], &b[jj][2]);
                }
            }
        }
        __syncthreads();
        if (k + FSTG < FNCH) load_chunk(k + FSTG);
        CP_COMMIT();
    }

    // --- epilogue: direct STG, float2 per (row, 2-col) pair ---
    const size_t rbase = m0 + (size_t)(wm * 64) + (size_t)(lane >> 2);
    const size_t cbase = n0 + (size_t)(wn * 32) + (size_t)((lane & 3) * 2);
#pragma unroll
    for (int i = 0; i < 4; i++) {
#pragma unroll
        for (int j = 0; j < 4; j++) {
            size_t row = rbase + (size_t)(i * 16);
            size_t col = cbase + (size_t)(j * 8);
            float2 v0 = make_float2(c[i][j][0], c[i][j][1]);
            float2 v1 = make_float2(c[i][j][2], c[i][j][3]);
            *reinterpret_cast<float2*>(out + row * O_DIM + col) = v0;
            *reinterpret_cast<float2*>(out + (row + 8) * O_DIM + col) = v1;
        }
    }
#endif  // !TCG_OK
}

// ---------------------------------------------------------------------------
// Launch: prep, then both GEMM kernels (exactly one has a body at runtime)
// ---------------------------------------------------------------------------
extern "C" void kernel_launch(void* const* d_in, const int* in_sizes, int n_in,
                              void* d_out, int out_size) {
    const float* x   = (const float*)d_in[0];
    const float* w   = (const float*)d_in[1];
    const float* pba = (const float*)d_in[2];
    const float* gam = (const float*)d_in[3];
    float* out = (float*)d_out;

    cudaFuncSetAttribute(nvfp4_gemm_tcgen05,
                         cudaFuncAttributeMaxDynamicSharedMemorySize, SMEM_DYN);
    cudaFuncSetAttribute(nvfp4_gemm_mmasync,
                         cudaFuncAttributeMaxDynamicSharedMemorySize, F_SMEM);

    {
        size_t n = (size_t)O_DIM * I_DIM;
        dequant_weight_kernel<<<(unsigned)((n + 255) / 256), 256>>>(w, pba, gam);
    }
    {
        size_t n = (size_t)T_DIM * I_DIM;
        split_x_kernel<<<(unsigned)((n + 255) / 256), 256>>>(x);
    }
    {
        dim3 grid(O_DIM / BN, T_DIM / BM, 1);     // tcgen05 tiling (16, 64)
        nvfp4_gemm_tcgen05<<<grid, 256, SMEM_DYN>>>(out);
    }
    {
        dim3 grid(O_DIM / FBN, T_DIM / FBM, 1);   // mma.sync tiling (32, 64)
        nvfp4_gemm_mmasync<<<grid, 256, F_SMEM>>>(out);
    }
}